// round 1
// baseline (speedup 1.0000x reference)
#include <cuda_runtime.h>
#include <cuda_bf16.h>
#include <cstdint>

// Problem constants
#define BATCH 16
#define CH    128
#define HH    64
#define WW    64
#define HW    4096          // 64*64
#define CQ    16            // C/8
#define CV    64            // C/2
#define TT    1024          // HW/4 pooled positions
#define NEG_INF (-3.402823466e38f)

// ---------------- scratch (static device memory; no allocs allowed) ----------------
__device__ float g_Wt[CQ * CH];     // normalized theta weight  [16,128]
__device__ float g_Wp[CQ * CH];     // normalized phi weight    [16,128]
__device__ float g_Wg[CV * CH];     // normalized g weight      [64,128]
__device__ float g_Wo[CH * CV];     // normalized o weight      [128,64]

__device__ float d_theta[BATCH * HW * CQ];   // [b][s][16]
__device__ float d_phi[BATCH * TT * CQ];     // [b][t][16]
__device__ float d_g[BATCH * TT * CV];       // [b][t][64]
__device__ float d_o[BATCH * HW * CV];       // [b][s][64]

// ---------------- packed f32x2 helpers (sm_103a) ----------------
__device__ __forceinline__ unsigned long long pack2(float v) {
    unsigned long long r;
    unsigned int u = __float_as_uint(v);
    asm("mov.b64 %0, {%1, %1};" : "=l"(r) : "r"(u));
    return r;
}
__device__ __forceinline__ void fma2(unsigned long long& d, unsigned long long a, unsigned long long b) {
    asm("fma.rn.f32x2 %0, %1, %2, %0;" : "+l"(d) : "l"(a), "l"(b));
}
__device__ __forceinline__ float2 unpack2(unsigned long long v) {
    float2 r;
    r.x = __uint_as_float((unsigned int)(v & 0xffffffffull));
    r.y = __uint_as_float((unsigned int)(v >> 32));
    return r;
}

// dot of 16 floats using packed f32x2 (q in regs as 8 packed pairs, k from smem)
__device__ __forceinline__ float dot16x2(const unsigned long long q2[8], const float* kp) {
    ulonglong2 ka = *(const ulonglong2*)(kp);
    ulonglong2 kb = *(const ulonglong2*)(kp + 4);
    ulonglong2 kc = *(const ulonglong2*)(kp + 8);
    ulonglong2 kd = *(const ulonglong2*)(kp + 12);
    unsigned long long d;
    asm("mul.rn.f32x2 %0, %1, %2;" : "=l"(d) : "l"(q2[0]), "l"(ka.x));
    asm("fma.rn.f32x2 %0, %1, %2, %0;" : "+l"(d) : "l"(q2[1]), "l"(ka.y));
    asm("fma.rn.f32x2 %0, %1, %2, %0;" : "+l"(d) : "l"(q2[2]), "l"(kb.x));
    asm("fma.rn.f32x2 %0, %1, %2, %0;" : "+l"(d) : "l"(q2[3]), "l"(kb.y));
    asm("fma.rn.f32x2 %0, %1, %2, %0;" : "+l"(d) : "l"(q2[4]), "l"(kc.x));
    asm("fma.rn.f32x2 %0, %1, %2, %0;" : "+l"(d) : "l"(q2[5]), "l"(kc.y));
    asm("fma.rn.f32x2 %0, %1, %2, %0;" : "+l"(d) : "l"(q2[6]), "l"(kd.x));
    asm("fma.rn.f32x2 %0, %1, %2, %0;" : "+l"(d) : "l"(q2[7]), "l"(kd.y));
    float2 f = unpack2(d);
    return f.x + f.y;
}

// ---------------- spectral norm ----------------
__device__ __forceinline__ float block_reduce_sum_128(float v, float* sred) {
    int t = threadIdx.x;
    sred[t] = v;
    __syncthreads();
    #pragma unroll
    for (int s = 64; s > 0; s >>= 1) {
        if (t < s) sred[t] += sred[t + s];
        __syncthreads();
    }
    float r = sred[0];
    __syncthreads();
    return r;
}

__global__ void sn_kernel(const float* w_theta, const float* w_phi,
                          const float* w_g, const float* w_o,
                          const float* u_theta, const float* u_phi,
                          const float* u_g, const float* u_o) {
    __shared__ float sv[128];
    __shared__ float sred[128];
    const float* W; const float* u; float* Wn; int O, I;
    switch (blockIdx.x) {
        case 0:  W = w_theta; u = u_theta; Wn = g_Wt; O = CQ; I = CH; break;
        case 1:  W = w_phi;   u = u_phi;   Wn = g_Wp; O = CQ; I = CH; break;
        case 2:  W = w_g;     u = u_g;     Wn = g_Wg; O = CV; I = CH; break;
        default: W = w_o;     u = u_o;     Wn = g_Wo; O = CH; I = CV; break;
    }
    int t = threadIdx.x;
    // v_raw = u @ W  (len I)
    float vr = 0.f;
    if (t < I) {
        for (int o = 0; o < O; o++) vr += u[o] * W[o * I + t];
    }
    float nv2 = block_reduce_sum_128((t < I) ? vr * vr : 0.f, sred);
    float inv = 1.f / fmaxf(sqrtf(nv2), 1e-12f);
    if (t < I) sv[t] = vr * inv;
    __syncthreads();
    // u2_raw = v @ W^T (len O)
    float ur = 0.f;
    if (t < O) {
        for (int i = 0; i < I; i++) ur += sv[i] * W[t * I + i];
    }
    float nu2 = block_reduce_sum_128((t < O) ? ur * ur : 0.f, sred);
    float invu = 1.f / fmaxf(sqrtf(nu2), 1e-12f);
    // sigma = sum_o (ur[o]*invu) * ur[o]
    float sigma = block_reduce_sum_128((t < O) ? ur * ur * invu : 0.f, sred);
    float wscale = 1.f / sigma;
    for (int k = t; k < O * I; k += 128) Wn[k] = W[k] * wscale;
}

// ---------------- theta conv: [16 out] per pixel, layout [b][s][16] ----------------
__global__ __launch_bounds__(256) void theta_kernel(const float* __restrict__ x) {
    __shared__ float sW[CQ * CH];
    for (int i = threadIdx.x; i < CQ * CH / 4; i += 256)
        ((float4*)sW)[i] = ((const float4*)g_Wt)[i];
    __syncthreads();
    int p = blockIdx.x * 256 + threadIdx.x;          // 0..65535
    int b = p >> 12, s = p & 4095;
    const float* xp = x + (size_t)b * CH * HW + s;
    float acc[CQ];
    #pragma unroll
    for (int o = 0; o < CQ; o++) acc[o] = 0.f;
    for (int c = 0; c < CH; c += 4) {
        float x0 = xp[(c + 0) * HW];
        float x1 = xp[(c + 1) * HW];
        float x2 = xp[(c + 2) * HW];
        float x3 = xp[(c + 3) * HW];
        #pragma unroll
        for (int o = 0; o < CQ; o++) {
            float4 w = *(const float4*)&sW[o * CH + c];
            acc[o] += w.x * x0 + w.y * x1 + w.z * x2 + w.w * x3;
        }
    }
    float4* outp = (float4*)&d_theta[(size_t)p * CQ];
    #pragma unroll
    for (int j = 0; j < 4; j++)
        outp[j] = make_float4(acc[4*j], acc[4*j+1], acc[4*j+2], acc[4*j+3]);
}

// ---------------- pooled convs (phi: NOUT=16, g: NOUT=32 x 2 groups) ----------------
template <int NOUT, int WSEL>
__global__ __launch_bounds__(128) void poolconv_kernel(const float* __restrict__ x) {
    __shared__ float sW[NOUT * CH];
    int ochOff = blockIdx.y * NOUT;
    const float* Wsrc = (WSEL == 0 ? g_Wp : g_Wg) + ochOff * CH;
    for (int i = threadIdx.x; i < NOUT * CH / 4; i += 128)
        ((float4*)sW)[i] = ((const float4*)Wsrc)[i];
    __syncthreads();
    int gidx = blockIdx.x * 128 + threadIdx.x;       // pooled pos 0..16383
    int b = gidx >> 10, t = gidx & 1023;
    int hp = t >> 5, wp = t & 31;
    int s00 = (hp * 2) * WW + wp * 2;
    const float* xb = x + (size_t)b * CH * HW;
    float pooled[NOUT];
    #pragma unroll
    for (int o = 0; o < NOUT; o++) pooled[o] = NEG_INF;
    int offs[4] = {s00, s00 + 1, s00 + WW, s00 + WW + 1};
    for (int pi = 0; pi < 4; pi++) {
        const float* xp = xb + offs[pi];
        float acc[NOUT];
        #pragma unroll
        for (int o = 0; o < NOUT; o++) acc[o] = 0.f;
        for (int c = 0; c < CH; c += 4) {
            float x0 = xp[(c + 0) * HW];
            float x1 = xp[(c + 1) * HW];
            float x2 = xp[(c + 2) * HW];
            float x3 = xp[(c + 3) * HW];
            #pragma unroll
            for (int o = 0; o < NOUT; o++) {
                float4 w = *(const float4*)&sW[o * CH + c];
                acc[o] += w.x * x0 + w.y * x1 + w.z * x2 + w.w * x3;
            }
        }
        #pragma unroll
        for (int o = 0; o < NOUT; o++) pooled[o] = fmaxf(pooled[o], acc[o]);
    }
    float* outp = (WSEL == 0) ? &d_phi[(size_t)gidx * CQ + ochOff]
                              : &d_g[(size_t)gidx * CV + ochOff];
    #pragma unroll
    for (int o = 0; o < NOUT; o += 4)
        *(float4*)&outp[o] = make_float4(pooled[o], pooled[o+1], pooled[o+2], pooled[o+3]);
}

// ---------------- attention (flash-style, 2-phase exact softmax) ----------------
#define ACHUNK 128
__global__ __launch_bounds__(128, 4) void attn_kernel() {
    __shared__ float Ks[ACHUNK * CQ];    // 8 KB
    __shared__ float Vs[ACHUNK * CV];    // 32 KB
    int q = blockIdx.x * 128 + threadIdx.x;  // global query 0..65535
    int b = q >> 12;
    const float* phib = &d_phi[(size_t)(b << 10) * CQ];
    const float* gb   = &d_g[(size_t)(b << 10) * CV];

    // load q (16 floats) as 8 packed f32x2
    const ulonglong2* qp = (const ulonglong2*)&d_theta[(size_t)q * CQ];
    ulonglong2 qa = qp[0], qb = qp[1], qc = qp[2], qd = qp[3];
    unsigned long long q2[8] = {qa.x, qa.y, qb.x, qb.y, qc.x, qc.y, qd.x, qd.y};

    // ---- Phase A: row max ----
    float m = NEG_INF;
    for (int c0 = 0; c0 < TT; c0 += ACHUNK) {
        __syncthreads();
        const float4* src = (const float4*)(phib + c0 * CQ);
        for (int i = threadIdx.x; i < ACHUNK * CQ / 4; i += 128)
            ((float4*)Ks)[i] = src[i];
        __syncthreads();
        #pragma unroll 4
        for (int t = 0; t < ACHUNK; t++) {
            float s = dot16x2(q2, &Ks[t * CQ]);
            m = fmaxf(m, s);
        }
    }

    // ---- Phase B: exp + accumulate ----
    unsigned long long acc[32];
    #pragma unroll
    for (int j = 0; j < 32; j++) acc[j] = 0ull;
    float l = 0.f;
    for (int c0 = 0; c0 < TT; c0 += ACHUNK) {
        __syncthreads();
        const float4* ksrc = (const float4*)(phib + c0 * CQ);
        for (int i = threadIdx.x; i < ACHUNK * CQ / 4; i += 128)
            ((float4*)Ks)[i] = ksrc[i];
        const float4* vsrc = (const float4*)(gb + c0 * CV);
        for (int i = threadIdx.x; i < ACHUNK * CV / 4; i += 128)
            ((float4*)Vs)[i] = vsrc[i];
        __syncthreads();
        for (int t = 0; t < ACHUNK; t++) {
            float s = dot16x2(q2, &Ks[t * CQ]);
            float p = __expf(s - m);
            l += p;
            unsigned long long P = pack2(p);
            const float* vp = &Vs[t * CV];
            #pragma unroll
            for (int j = 0; j < 16; j++) {
                ulonglong2 v = *(const ulonglong2*)(vp + j * 4);
                fma2(acc[2*j],     v.x, P);
                fma2(acc[2*j + 1], v.y, P);
            }
        }
    }
    float invl = 1.f / l;
    float4* outp = (float4*)&d_o[(size_t)q * CV];
    #pragma unroll
    for (int j = 0; j < 16; j++) {
        float2 a0 = unpack2(acc[2*j]);
        float2 a1 = unpack2(acc[2*j + 1]);
        outp[j] = make_float4(a0.x * invl, a0.y * invl, a1.x * invl, a1.y * invl);
    }
}

// ---------------- output conv + residual: out = gamma * Wo @ o + x ----------------
__global__ __launch_bounds__(256) void oconv_kernel(const float* __restrict__ x,
                                                    const float* __restrict__ gptr,
                                                    float* __restrict__ out) {
    __shared__ float sW[CV * 32];   // transposed [c][j]: j = local out channel
    int gy = blockIdx.y;            // out-channel group (32 each)
    for (int i = threadIdx.x; i < CV * 32; i += 256) {
        int c = i >> 5, j = i & 31;
        sW[c * 32 + j] = g_Wo[(32 * gy + j) * CV + c];
    }
    __syncthreads();
    float gamma = *gptr;
    int p = blockIdx.x * 256 + threadIdx.x;   // pixel 0..65535
    int b = p >> 12, s = p & 4095;
    const float4* op = (const float4*)&d_o[(size_t)p * CV];

    unsigned long long acc[16];
    #pragma unroll
    for (int j = 0; j < 16; j++) acc[j] = 0ull;

    for (int c4 = 0; c4 < 16; c4++) {
        float4 xv = op[c4];
        float vals[4] = {xv.x, xv.y, xv.z, xv.w};
        #pragma unroll
        for (int cc = 0; cc < 4; cc++) {
            int c = c4 * 4 + cc;
            unsigned long long X = pack2(vals[cc]);
            const float* wr = &sW[c * 32];
            #pragma unroll
            for (int j = 0; j < 8; j++) {
                ulonglong2 w = *(const ulonglong2*)(wr + j * 4);
                fma2(acc[2*j],     w.x, X);
                fma2(acc[2*j + 1], w.y, X);
            }
        }
    }
    size_t base = ((size_t)(b * CH + 32 * gy)) * HW + s;
    #pragma unroll
    for (int j = 0; j < 16; j++) {
        float2 a = unpack2(acc[j]);
        size_t i0 = base + (size_t)(2 * j) * HW;
        size_t i1 = base + (size_t)(2 * j + 1) * HW;
        out[i0] = gamma * a.x + x[i0];
        out[i1] = gamma * a.y + x[i1];
    }
}

// ---------------- launch ----------------
extern "C" void kernel_launch(void* const* d_in, const int* in_sizes, int n_in,
                              void* d_out, int out_size) {
    const float* x       = (const float*)d_in[0];
    const float* w_theta = (const float*)d_in[1];
    const float* w_phi   = (const float*)d_in[2];
    const float* w_g     = (const float*)d_in[3];
    const float* w_o     = (const float*)d_in[4];
    const float* u_theta = (const float*)d_in[5];
    const float* u_phi   = (const float*)d_in[6];
    const float* u_g     = (const float*)d_in[7];
    const float* u_o     = (const float*)d_in[8];
    const float* gamma   = (const float*)d_in[9];
    float* out = (float*)d_out;

    sn_kernel<<<4, 128>>>(w_theta, w_phi, w_g, w_o, u_theta, u_phi, u_g, u_o);
    theta_kernel<<<256, 256>>>(x);
    poolconv_kernel<16, 0><<<dim3(128, 1), 128>>>(x);
    poolconv_kernel<32, 1><<<dim3(128, 2), 128>>>(x);
    attn_kernel<<<512, 128>>>();
    oconv_kernel<<<dim3(256, 4), 256>>>(x, gamma, out);
}

// round 2
// speedup vs baseline: 1.2934x; 1.2934x over previous
#include <cuda_runtime.h>
#include <cuda_bf16.h>
#include <cstdint>

// Problem constants
#define BATCH 16
#define CH    128
#define HH    64
#define WW    64
#define HW    4096          // 64*64
#define CQ    16            // C/8
#define CV    64            // C/2
#define TT    1024          // HW/4 pooled positions
#define NEG_INF (-3.402823466e38f)

typedef unsigned long long ull;

// ---------------- scratch (static device memory; no allocs allowed) ----------------
__device__ float g_Wt[CQ * CH];     // normalized theta weight  [16,128]
__device__ float g_Wp[CQ * CH];     // normalized phi weight    [16,128]
__device__ float g_Wg[CV * CH];     // normalized g weight      [64,128]
__device__ float g_Wo[CH * CV];     // normalized o weight      [128,64]

__device__ float d_theta[BATCH * HW * CQ];   // [b][s][16]
__device__ float d_phi[BATCH * TT * CQ];     // [b][t][16]
__device__ float d_g[BATCH * TT * CV];       // [b][t][64]
__device__ float d_o[BATCH * HW * CV];       // [b][s][64]

// ---------------- packed f32x2 helpers (sm_103a) ----------------
__device__ __forceinline__ ull pack2(float v) {
    ull r;
    unsigned int u = __float_as_uint(v);
    asm("mov.b64 %0, {%1, %1};" : "=l"(r) : "r"(u));
    return r;
}
__device__ __forceinline__ void fma2(ull& d, ull a, ull b) {
    asm("fma.rn.f32x2 %0, %1, %2, %0;" : "+l"(d) : "l"(a), "l"(b));
}
__device__ __forceinline__ void mul2(ull& d, ull s) {
    asm("mul.rn.f32x2 %0, %0, %1;" : "+l"(d) : "l"(s));
}
__device__ __forceinline__ float2 unpack2(ull v) {
    float2 r;
    r.x = __uint_as_float((unsigned int)(v & 0xffffffffull));
    r.y = __uint_as_float((unsigned int)(v >> 32));
    return r;
}

// dot of 16 floats using packed f32x2 (q in regs as 8 packed pairs, k from smem)
__device__ __forceinline__ float dot16x2(const ull q2[8], const float* kp) {
    ulonglong2 ka = *(const ulonglong2*)(kp);
    ulonglong2 kb = *(const ulonglong2*)(kp + 4);
    ulonglong2 kc = *(const ulonglong2*)(kp + 8);
    ulonglong2 kd = *(const ulonglong2*)(kp + 12);
    ull d;
    asm("mul.rn.f32x2 %0, %1, %2;" : "=l"(d) : "l"(q2[0]), "l"(ka.x));
    asm("fma.rn.f32x2 %0, %1, %2, %0;" : "+l"(d) : "l"(q2[1]), "l"(ka.y));
    asm("fma.rn.f32x2 %0, %1, %2, %0;" : "+l"(d) : "l"(q2[2]), "l"(kb.x));
    asm("fma.rn.f32x2 %0, %1, %2, %0;" : "+l"(d) : "l"(q2[3]), "l"(kb.y));
    asm("fma.rn.f32x2 %0, %1, %2, %0;" : "+l"(d) : "l"(q2[4]), "l"(kc.x));
    asm("fma.rn.f32x2 %0, %1, %2, %0;" : "+l"(d) : "l"(q2[5]), "l"(kc.y));
    asm("fma.rn.f32x2 %0, %1, %2, %0;" : "+l"(d) : "l"(q2[6]), "l"(kd.x));
    asm("fma.rn.f32x2 %0, %1, %2, %0;" : "+l"(d) : "l"(q2[7]), "l"(kd.y));
    float2 f = unpack2(d);
    return f.x + f.y;
}

// ---------------- spectral norm ----------------
__device__ __forceinline__ float block_reduce_sum_128(float v, float* sred) {
    int t = threadIdx.x;
    sred[t] = v;
    __syncthreads();
    #pragma unroll
    for (int s = 64; s > 0; s >>= 1) {
        if (t < s) sred[t] += sred[t + s];
        __syncthreads();
    }
    float r = sred[0];
    __syncthreads();
    return r;
}

__global__ void sn_kernel(const float* w_theta, const float* w_phi,
                          const float* w_g, const float* w_o,
                          const float* u_theta, const float* u_phi,
                          const float* u_g, const float* u_o) {
    __shared__ float sv[128];
    __shared__ float sred[128];
    const float* W; const float* u; float* Wn; int O, I;
    switch (blockIdx.x) {
        case 0:  W = w_theta; u = u_theta; Wn = g_Wt; O = CQ; I = CH; break;
        case 1:  W = w_phi;   u = u_phi;   Wn = g_Wp; O = CQ; I = CH; break;
        case 2:  W = w_g;     u = u_g;     Wn = g_Wg; O = CV; I = CH; break;
        default: W = w_o;     u = u_o;     Wn = g_Wo; O = CH; I = CV; break;
    }
    int t = threadIdx.x;
    // v_raw = u @ W  (len I)
    float vr = 0.f;
    if (t < I) {
        for (int o = 0; o < O; o++) vr += u[o] * W[o * I + t];
    }
    float nv2 = block_reduce_sum_128((t < I) ? vr * vr : 0.f, sred);
    float inv = 1.f / fmaxf(sqrtf(nv2), 1e-12f);
    if (t < I) sv[t] = vr * inv;
    __syncthreads();
    // u2_raw = v @ W^T (len O)
    float ur = 0.f;
    if (t < O) {
        for (int i = 0; i < I; i++) ur += sv[i] * W[t * I + i];
    }
    float nu2 = block_reduce_sum_128((t < O) ? ur * ur : 0.f, sred);
    float invu = 1.f / fmaxf(sqrtf(nu2), 1e-12f);
    // sigma = sum_o (ur[o]*invu) * ur[o]
    float sigma = block_reduce_sum_128((t < O) ? ur * ur * invu : 0.f, sred);
    float wscale = 1.f / sigma;
    for (int k = t; k < O * I; k += 128) Wn[k] = W[k] * wscale;
}

// ---------------- theta conv: [16 out] per pixel, layout [b][s][16] ----------------
__global__ __launch_bounds__(256) void theta_kernel(const float* __restrict__ x) {
    __shared__ float sW[CH * CQ];   // transposed [c][o]
    for (int i = threadIdx.x; i < CH * CQ; i += 256) {
        int c = i >> 4, o = i & 15;
        sW[i] = g_Wt[o * CH + c];
    }
    __syncthreads();
    int p = blockIdx.x * 256 + threadIdx.x;          // 0..65535
    int b = p >> 12, s = p & 4095;
    const float* xp = x + (size_t)b * CH * HW + s;
    ull acc[8];
    #pragma unroll
    for (int j = 0; j < 8; j++) acc[j] = 0ull;
    #pragma unroll 4
    for (int c = 0; c < CH; c++) {
        ull X = pack2(xp[c * HW]);
        const float* wr = &sW[c * CQ];
        #pragma unroll
        for (int j = 0; j < 4; j++) {
            ulonglong2 w = *(const ulonglong2*)(wr + j * 4);
            fma2(acc[2*j],     w.x, X);
            fma2(acc[2*j + 1], w.y, X);
        }
    }
    float4* outp = (float4*)&d_theta[(size_t)p * CQ];
    #pragma unroll
    for (int j = 0; j < 4; j++) {
        float2 a0 = unpack2(acc[2*j]);
        float2 a1 = unpack2(acc[2*j + 1]);
        outp[j] = make_float4(a0.x, a0.y, a1.x, a1.y);
    }
}

// ---------------- pooled convs: 1 thread per (pooled pos, subpixel) ----------------
// phi: NOUT=16, one y-group.  g: NOUT=32, two y-groups.
template <int NOUT, int WSEL>
__global__ __launch_bounds__(128) void poolconv_kernel(const float* __restrict__ x) {
    __shared__ float sW[CH * NOUT];  // transposed [c][o]
    int ochOff = blockIdx.y * NOUT;
    const float* Wsrc = (WSEL == 0 ? g_Wp : g_Wg);
    for (int i = threadIdx.x; i < CH * NOUT; i += 128) {
        int c = i / NOUT, o = i % NOUT;
        sW[i] = Wsrc[(ochOff + o) * CH + c];
    }
    __syncthreads();
    int tid = blockIdx.x * 128 + threadIdx.x;   // 0..65535
    int pooled = tid >> 2, sub = tid & 3;       // pooled pos 0..16383, subpixel 0..3
    int b = pooled >> 10, t = pooled & 1023;
    int hp = t >> 5, wp = t & 31;
    int pix = (2 * hp + (sub >> 1)) * WW + 2 * wp + (sub & 1);
    const float* xp = x + (size_t)b * CH * HW + pix;

    ull acc[NOUT / 2];
    #pragma unroll
    for (int j = 0; j < NOUT / 2; j++) acc[j] = 0ull;

    #pragma unroll 4
    for (int c = 0; c < CH; c++) {
        ull X = pack2(xp[c * HW]);
        const float* wr = &sW[c * NOUT];
        #pragma unroll
        for (int j = 0; j < NOUT / 4; j++) {
            ulonglong2 w = *(const ulonglong2*)(wr + j * 4);
            fma2(acc[2*j],     w.x, X);
            fma2(acc[2*j + 1], w.y, X);
        }
    }

    // max over the 4 subpixels (lanes grouped by low 2 bits)
    float vals[NOUT];
    #pragma unroll
    for (int j = 0; j < NOUT / 2; j++) {
        float2 f = unpack2(acc[j]);
        vals[2*j] = f.x; vals[2*j + 1] = f.y;
    }
    #pragma unroll
    for (int o = 0; o < NOUT; o++) {
        vals[o] = fmaxf(vals[o], __shfl_xor_sync(0xffffffffu, vals[o], 1));
        vals[o] = fmaxf(vals[o], __shfl_xor_sync(0xffffffffu, vals[o], 2));
    }
    if (sub == 0) {
        float* outp = (WSEL == 0) ? &d_phi[(size_t)pooled * CQ + ochOff]
                                  : &d_g[(size_t)pooled * CV + ochOff];
        #pragma unroll
        for (int o = 0; o < NOUT; o += 4)
            *(float4*)&outp[o] = make_float4(vals[o], vals[o+1], vals[o+2], vals[o+3]);
    }
}

// ---------------- attention: single-pass online softmax ----------------
#define ACHUNK 64
__global__ __launch_bounds__(128, 4) void attn_kernel() {
    __shared__ float Ks[ACHUNK * CQ];    // 4 KB
    __shared__ float Vs[ACHUNK * CV];    // 16 KB
    int q = blockIdx.x * 128 + threadIdx.x;  // global query 0..65535
    int b = q >> 12;
    const float* phib = &d_phi[(size_t)(b << 10) * CQ];
    const float* gb   = &d_g[(size_t)(b << 10) * CV];

    // load q (16 floats) as 8 packed f32x2
    const ulonglong2* qp = (const ulonglong2*)&d_theta[(size_t)q * CQ];
    ulonglong2 qa = qp[0], qb = qp[1], qc = qp[2], qd = qp[3];
    ull q2[8] = {qa.x, qa.y, qb.x, qb.y, qc.x, qc.y, qd.x, qd.y};

    ull acc[32];
    #pragma unroll
    for (int j = 0; j < 32; j++) acc[j] = 0ull;
    float m = NEG_INF, l = 0.f;

    for (int c0 = 0; c0 < TT; c0 += ACHUNK) {
        __syncthreads();
        const float4* ksrc = (const float4*)(phib + c0 * CQ);
        for (int i = threadIdx.x; i < ACHUNK * CQ / 4; i += 128)
            ((float4*)Ks)[i] = ksrc[i];
        const float4* vsrc = (const float4*)(gb + c0 * CV);
        for (int i = threadIdx.x; i < ACHUNK * CV / 4; i += 128)
            ((float4*)Vs)[i] = vsrc[i];
        __syncthreads();

        for (int t0 = 0; t0 < ACHUNK; t0 += 8) {
            float dots[8];
            #pragma unroll
            for (int i = 0; i < 8; i++)
                dots[i] = dot16x2(q2, &Ks[(t0 + i) * CQ]);
            float t01 = fmaxf(dots[0], dots[1]);
            float t23 = fmaxf(dots[2], dots[3]);
            float t45 = fmaxf(dots[4], dots[5]);
            float t67 = fmaxf(dots[6], dots[7]);
            float tmax = fmaxf(fmaxf(t01, t23), fmaxf(t45, t67));
            if (tmax > m) {
                float sc = __expf(m - tmax);   // exp(-inf) = 0 handles init
                l *= sc;
                ull S = pack2(sc);
                #pragma unroll
                for (int j = 0; j < 32; j++) mul2(acc[j], S);
                m = tmax;
            }
            #pragma unroll
            for (int i = 0; i < 8; i++) {
                float p = __expf(dots[i] - m);
                l += p;
                ull P = pack2(p);
                const float* vp = &Vs[(t0 + i) * CV];
                #pragma unroll
                for (int j = 0; j < 16; j++) {
                    ulonglong2 v = *(const ulonglong2*)(vp + j * 4);
                    fma2(acc[2*j],     v.x, P);
                    fma2(acc[2*j + 1], v.y, P);
                }
            }
        }
    }
    float invl = 1.f / l;
    float4* outp = (float4*)&d_o[(size_t)q * CV];
    #pragma unroll
    for (int j = 0; j < 16; j++) {
        float2 a0 = unpack2(acc[2*j]);
        float2 a1 = unpack2(acc[2*j + 1]);
        outp[j] = make_float4(a0.x * invl, a0.y * invl, a1.x * invl, a1.y * invl);
    }
}

// ---------------- output conv + residual: out = gamma * Wo @ o + x ----------------
__global__ __launch_bounds__(256) void oconv_kernel(const float* __restrict__ x,
                                                    const float* __restrict__ gptr,
                                                    float* __restrict__ out) {
    __shared__ float sW[CV * 32];   // transposed [c][j]: j = local out channel
    int gy = blockIdx.y;            // out-channel group (32 each)
    for (int i = threadIdx.x; i < CV * 32; i += 256) {
        int c = i >> 5, j = i & 31;
        sW[c * 32 + j] = g_Wo[(32 * gy + j) * CV + c];
    }
    __syncthreads();
    float gamma = *gptr;
    int p = blockIdx.x * 256 + threadIdx.x;   // pixel 0..65535
    int b = p >> 12, s = p & 4095;
    const float4* op = (const float4*)&d_o[(size_t)p * CV];

    ull acc[16];
    #pragma unroll
    for (int j = 0; j < 16; j++) acc[j] = 0ull;

    for (int c4 = 0; c4 < 16; c4++) {
        float4 xv = op[c4];
        float vals[4] = {xv.x, xv.y, xv.z, xv.w};
        #pragma unroll
        for (int cc = 0; cc < 4; cc++) {
            int c = c4 * 4 + cc;
            ull X = pack2(vals[cc]);
            const float* wr = &sW[c * 32];
            #pragma unroll
            for (int j = 0; j < 8; j++) {
                ulonglong2 w = *(const ulonglong2*)(wr + j * 4);
                fma2(acc[2*j],     w.x, X);
                fma2(acc[2*j + 1], w.y, X);
            }
        }
    }
    size_t base = ((size_t)(b * CH + 32 * gy)) * HW + s;
    #pragma unroll
    for (int j = 0; j < 16; j++) {
        float2 a = unpack2(acc[j]);
        size_t i0 = base + (size_t)(2 * j) * HW;
        size_t i1 = base + (size_t)(2 * j + 1) * HW;
        out[i0] = gamma * a.x + x[i0];
        out[i1] = gamma * a.y + x[i1];
    }
}

// ---------------- launch ----------------
extern "C" void kernel_launch(void* const* d_in, const int* in_sizes, int n_in,
                              void* d_out, int out_size) {
    const float* x       = (const float*)d_in[0];
    const float* w_theta = (const float*)d_in[1];
    const float* w_phi   = (const float*)d_in[2];
    const float* w_g     = (const float*)d_in[3];
    const float* w_o     = (const float*)d_in[4];
    const float* u_theta = (const float*)d_in[5];
    const float* u_phi   = (const float*)d_in[6];
    const float* u_g     = (const float*)d_in[7];
    const float* u_o     = (const float*)d_in[8];
    const float* gamma   = (const float*)d_in[9];
    float* out = (float*)d_out;

    sn_kernel<<<4, 128>>>(w_theta, w_phi, w_g, w_o, u_theta, u_phi, u_g, u_o);
    theta_kernel<<<256, 256>>>(x);
    poolconv_kernel<16, 0><<<dim3(512, 1), 128>>>(x);
    poolconv_kernel<32, 1><<<dim3(512, 2), 128>>>(x);
    attn_kernel<<<512, 128>>>();
    oconv_kernel<<<dim3(256, 4), 256>>>(x, gamma, out);
}

// round 3
// speedup vs baseline: 2.4783x; 1.9161x over previous
#include <cuda_runtime.h>
#include <cuda_bf16.h>
#include <cstdint>

// Problem constants
#define BATCH 16
#define CH    128
#define HH    64
#define WW    64
#define HW    4096          // 64*64
#define CQ    16            // C/8
#define CV    64            // C/2
#define TT    1024          // HW/4 pooled positions
#define NEG_INF (-3.402823466e38f)

typedef unsigned long long ull;

// ---------------- scratch (static device memory; no allocs allowed) ----------------
__device__ float g_Wt[CQ * CH];     // normalized theta weight  [16,128]
__device__ float g_Wp[CQ * CH];     // normalized phi weight    [16,128]
__device__ float g_Wg[CV * CH];     // normalized g weight      [64,128]
__device__ float g_Wo[CH * CV];     // normalized o weight      [128,64]

__device__ float d_theta[BATCH * HW * CQ];   // [b][s][16]
__device__ float d_phi[BATCH * TT * CQ];     // [b][t][16]
__device__ float d_g[BATCH * TT * CV];       // [b][t][64]
__device__ float d_o[BATCH * HW * CV];       // [b][s][64]

// ---------------- packed f32x2 helpers (sm_103a) ----------------
__device__ __forceinline__ ull pack2(float v) {
    ull r;
    unsigned int u = __float_as_uint(v);
    asm("mov.b64 %0, {%1, %1};" : "=l"(r) : "r"(u));
    return r;
}
__device__ __forceinline__ void fma2(ull& d, ull a, ull b) {
    asm("fma.rn.f32x2 %0, %1, %2, %0;" : "+l"(d) : "l"(a), "l"(b));
}
__device__ __forceinline__ float2 unpack2(ull v) {
    float2 r;
    r.x = __uint_as_float((unsigned int)(v & 0xffffffffull));
    r.y = __uint_as_float((unsigned int)(v >> 32));
    return r;
}

__device__ __forceinline__ unsigned to_tf32(float f) {
    unsigned r;
    asm("cvt.rna.tf32.f32 %0, %1;" : "=r"(r) : "f"(f));
    return r;
}

// mma.sync m16n8k8 tf32, C += A*B
__device__ __forceinline__ void mma8(float c[4], const unsigned a[4],
                                     unsigned b0, unsigned b1) {
    asm("mma.sync.aligned.m16n8k8.row.col.f32.tf32.tf32.f32 "
        "{%0,%1,%2,%3}, {%4,%5,%6,%7}, {%8,%9}, {%0,%1,%2,%3};"
        : "+f"(c[0]), "+f"(c[1]), "+f"(c[2]), "+f"(c[3])
        : "r"(a[0]), "r"(a[1]), "r"(a[2]), "r"(a[3]), "r"(b0), "r"(b1));
}

// ---------------- spectral norm ----------------
__device__ __forceinline__ float block_reduce_sum_128(float v, float* sred) {
    int t = threadIdx.x;
    sred[t] = v;
    __syncthreads();
    #pragma unroll
    for (int s = 64; s > 0; s >>= 1) {
        if (t < s) sred[t] += sred[t + s];
        __syncthreads();
    }
    float r = sred[0];
    __syncthreads();
    return r;
}

__global__ void sn_kernel(const float* w_theta, const float* w_phi,
                          const float* w_g, const float* w_o,
                          const float* u_theta, const float* u_phi,
                          const float* u_g, const float* u_o) {
    __shared__ float sv[128];
    __shared__ float sred[128];
    const float* W; const float* u; float* Wn; int O, I;
    switch (blockIdx.x) {
        case 0:  W = w_theta; u = u_theta; Wn = g_Wt; O = CQ; I = CH; break;
        case 1:  W = w_phi;   u = u_phi;   Wn = g_Wp; O = CQ; I = CH; break;
        case 2:  W = w_g;     u = u_g;     Wn = g_Wg; O = CV; I = CH; break;
        default: W = w_o;     u = u_o;     Wn = g_Wo; O = CH; I = CV; break;
    }
    int t = threadIdx.x;
    float vr = 0.f;
    if (t < I) {
        for (int o = 0; o < O; o++) vr += u[o] * W[o * I + t];
    }
    float nv2 = block_reduce_sum_128((t < I) ? vr * vr : 0.f, sred);
    float inv = 1.f / fmaxf(sqrtf(nv2), 1e-12f);
    if (t < I) sv[t] = vr * inv;
    __syncthreads();
    float ur = 0.f;
    if (t < O) {
        for (int i = 0; i < I; i++) ur += sv[i] * W[t * I + i];
    }
    float nu2 = block_reduce_sum_128((t < O) ? ur * ur : 0.f, sred);
    float invu = 1.f / fmaxf(sqrtf(nu2), 1e-12f);
    float sigma = block_reduce_sum_128((t < O) ? ur * ur * invu : 0.f, sred);
    float wscale = 1.f / sigma;
    for (int k = t; k < O * I; k += 128) Wn[k] = W[k] * wscale;
}

// ---------------- theta conv: [16 out] per pixel, layout [b][s][16] ----------------
__global__ __launch_bounds__(256) void theta_kernel(const float* __restrict__ x) {
    __shared__ float sW[CH * CQ];   // transposed [c][o]
    for (int i = threadIdx.x; i < CH * CQ; i += 256) {
        int c = i >> 4, o = i & 15;
        sW[i] = g_Wt[o * CH + c];
    }
    __syncthreads();
    int p = blockIdx.x * 256 + threadIdx.x;          // 0..65535
    int b = p >> 12, s = p & 4095;
    const float* xp = x + (size_t)b * CH * HW + s;
    ull acc[8];
    #pragma unroll
    for (int j = 0; j < 8; j++) acc[j] = 0ull;
    #pragma unroll 8
    for (int c = 0; c < CH; c++) {
        ull X = pack2(xp[c * HW]);
        const float* wr = &sW[c * CQ];
        #pragma unroll
        for (int j = 0; j < 4; j++) {
            ulonglong2 w = *(const ulonglong2*)(wr + j * 4);
            fma2(acc[2*j],     w.x, X);
            fma2(acc[2*j + 1], w.y, X);
        }
    }
    float4* outp = (float4*)&d_theta[(size_t)p * CQ];
    #pragma unroll
    for (int j = 0; j < 4; j++) {
        float2 a0 = unpack2(acc[2*j]);
        float2 a1 = unpack2(acc[2*j + 1]);
        outp[j] = make_float4(a0.x, a0.y, a1.x, a1.y);
    }
}

// ---------------- pooled convs: 1 thread per (pooled pos, subpixel) ----------------
template <int NOUT, int WSEL>
__global__ __launch_bounds__(128) void poolconv_kernel(const float* __restrict__ x) {
    __shared__ float sW[CH * NOUT];  // transposed [c][o]
    int ochOff = blockIdx.y * NOUT;
    const float* Wsrc = (WSEL == 0 ? g_Wp : g_Wg);
    for (int i = threadIdx.x; i < CH * NOUT; i += 128) {
        int c = i / NOUT, o = i % NOUT;
        sW[i] = Wsrc[(ochOff + o) * CH + c];
    }
    __syncthreads();
    int tid = blockIdx.x * 128 + threadIdx.x;   // 0..65535
    int pooled = tid >> 2, sub = tid & 3;       // pooled pos, subpixel
    int b = pooled >> 10, t = pooled & 1023;
    int hp = t >> 5, wp = t & 31;
    int pix = (2 * hp + (sub >> 1)) * WW + 2 * wp + (sub & 1);
    const float* xp = x + (size_t)b * CH * HW + pix;

    ull acc[NOUT / 2];
    #pragma unroll
    for (int j = 0; j < NOUT / 2; j++) acc[j] = 0ull;

    #pragma unroll 8
    for (int c = 0; c < CH; c++) {
        ull X = pack2(xp[c * HW]);
        const float* wr = &sW[c * NOUT];
        #pragma unroll
        for (int j = 0; j < NOUT / 4; j++) {
            ulonglong2 w = *(const ulonglong2*)(wr + j * 4);
            fma2(acc[2*j],     w.x, X);
            fma2(acc[2*j + 1], w.y, X);
        }
    }

    float vals[NOUT];
    #pragma unroll
    for (int j = 0; j < NOUT / 2; j++) {
        float2 f = unpack2(acc[j]);
        vals[2*j] = f.x; vals[2*j + 1] = f.y;
    }
    #pragma unroll
    for (int o = 0; o < NOUT; o++) {
        vals[o] = fmaxf(vals[o], __shfl_xor_sync(0xffffffffu, vals[o], 1));
        vals[o] = fmaxf(vals[o], __shfl_xor_sync(0xffffffffu, vals[o], 2));
    }
    if (sub == 0) {
        float* outp = (WSEL == 0) ? &d_phi[(size_t)pooled * CQ + ochOff]
                                  : &d_g[(size_t)pooled * CV + ochOff];
        #pragma unroll
        for (int o = 0; o < NOUT; o += 4)
            *(float4*)&outp[o] = make_float4(vals[o], vals[o+1], vals[o+2], vals[o+3]);
    }
}

// ---------------- attention: mma.sync tf32 flash kernel ----------------
// Block: 256 threads / 8 warps; 128 queries per block (warp = 16 query rows).
// K chunk [64x16] tf32 in smem (stride 20), V chunk [64x64] tf32 (stride 72).
#define SKS 20
#define SVS 72
__global__ __launch_bounds__(256, 2) void attn_mma_kernel() {
    __shared__ unsigned sK[64 * SKS];   // 5 KB
    __shared__ unsigned sV[64 * SVS];   // 18 KB
    const int tid = threadIdx.x;
    const int w = tid >> 5, lane = tid & 31;
    const int g = lane >> 2, l = lane & 3;
    const int qbase = blockIdx.x * 128 + w * 16;
    const int b = (int)((blockIdx.x * 128) >> 12);
    const float* phib = &d_phi[(size_t)(b << 10) * CQ];
    const float* gb   = &d_g[(size_t)(b << 10) * CV];

    // Q fragments (A operand, 2 k-steps), tf32
    unsigned qf[2][4];
    {
        const float* q0 = &d_theta[(size_t)(qbase + g) * CQ];
        const float* q1 = &d_theta[(size_t)(qbase + g + 8) * CQ];
        qf[0][0] = to_tf32(q0[l]);      qf[0][1] = to_tf32(q1[l]);
        qf[0][2] = to_tf32(q0[l + 4]);  qf[0][3] = to_tf32(q1[l + 4]);
        qf[1][0] = to_tf32(q0[8 + l]);  qf[1][1] = to_tf32(q1[8 + l]);
        qf[1][2] = to_tf32(q0[12 + l]); qf[1][3] = to_tf32(q1[12 + l]);
    }

    float o[8][4];
    #pragma unroll
    for (int nt = 0; nt < 8; nt++)
        #pragma unroll
        for (int j = 0; j < 4; j++) o[nt][j] = 0.f;
    float mA = NEG_INF, mB = NEG_INF, lA = 0.f, lB = 0.f;

    const unsigned s1 = (lane & ~3u) | ((unsigned)l >> 1);
    const unsigned s2 = s1 + 2;

    for (int c0 = 0; c0 < TT; c0 += 64) {
        __syncthreads();
        // fill K chunk (64 rows x 16), tf32
        {
            int row = tid >> 2, seg = tid & 3;
            float4 v = *(const float4*)&phib[(c0 + row) * CQ + seg * 4];
            uint4 u = make_uint4(to_tf32(v.x), to_tf32(v.y), to_tf32(v.z), to_tf32(v.w));
            *(uint4*)&sK[row * SKS + seg * 4] = u;
        }
        // fill V chunk (64 rows x 64), tf32
        #pragma unroll
        for (int r = 0; r < 4; r++) {
            int idx = tid + r * 256;
            int row = idx >> 4, seg = idx & 15;
            float4 v = *(const float4*)&gb[(c0 + row) * CV + seg * 4];
            uint4 u = make_uint4(to_tf32(v.x), to_tf32(v.y), to_tf32(v.z), to_tf32(v.w));
            *(uint4*)&sV[row * SVS + seg * 4] = u;
        }
        __syncthreads();

        // ---- S = Q @ K^T : 8 n-tiles x 2 k-steps ----
        float c[8][4];
        #pragma unroll
        for (int nt = 0; nt < 8; nt++) {
            c[nt][0] = c[nt][1] = c[nt][2] = c[nt][3] = 0.f;
            int krow = (nt * 8 + g) * SKS;
            mma8(c[nt], qf[0], sK[krow + l],     sK[krow + l + 4]);
            mma8(c[nt], qf[1], sK[krow + 8 + l], sK[krow + 12 + l]);
        }

        // ---- online softmax ----
        float cmA = NEG_INF, cmB = NEG_INF;
        #pragma unroll
        for (int nt = 0; nt < 8; nt++) {
            cmA = fmaxf(cmA, fmaxf(c[nt][0], c[nt][1]));
            cmB = fmaxf(cmB, fmaxf(c[nt][2], c[nt][3]));
        }
        cmA = fmaxf(cmA, __shfl_xor_sync(0xffffffffu, cmA, 1));
        cmA = fmaxf(cmA, __shfl_xor_sync(0xffffffffu, cmA, 2));
        cmB = fmaxf(cmB, __shfl_xor_sync(0xffffffffu, cmB, 1));
        cmB = fmaxf(cmB, __shfl_xor_sync(0xffffffffu, cmB, 2));
        float nmA = fmaxf(mA, cmA), nmB = fmaxf(mB, cmB);
        float sA = __expf(mA - nmA), sB = __expf(mB - nmB);
        mA = nmA; mB = nmB;
        lA *= sA; lB *= sB;

        unsigned p[8][4];
        #pragma unroll
        for (int nt = 0; nt < 8; nt++) {
            o[nt][0] *= sA; o[nt][1] *= sA; o[nt][2] *= sB; o[nt][3] *= sB;
            float p0 = __expf(c[nt][0] - mA);
            float p1 = __expf(c[nt][1] - mA);
            float p2 = __expf(c[nt][2] - mB);
            float p3 = __expf(c[nt][3] - mB);
            lA += p0 + p1; lB += p2 + p3;
            p[nt][0] = to_tf32(p0); p[nt][1] = to_tf32(p1);
            p[nt][2] = to_tf32(p2); p[nt][3] = to_tf32(p3);
        }

        // ---- O += P @ V : 8 k-blocks x 8 n-tiles ----
        #pragma unroll
        for (int kb = 0; kb < 8; kb++) {
            unsigned x0 = __shfl_sync(0xffffffffu, p[kb][0], s1);
            unsigned x1 = __shfl_sync(0xffffffffu, p[kb][1], s1);
            unsigned x2 = __shfl_sync(0xffffffffu, p[kb][2], s1);
            unsigned x3 = __shfl_sync(0xffffffffu, p[kb][3], s1);
            unsigned y0 = __shfl_sync(0xffffffffu, p[kb][0], s2);
            unsigned y1 = __shfl_sync(0xffffffffu, p[kb][1], s2);
            unsigned y2 = __shfl_sync(0xffffffffu, p[kb][2], s2);
            unsigned y3 = __shfl_sync(0xffffffffu, p[kb][3], s2);
            unsigned a[4];
            bool odd = (l & 1);
            a[0] = odd ? x1 : x0;   // P[g][kb*8 + l]
            a[1] = odd ? x3 : x2;   // P[g+8][kb*8 + l]
            a[2] = odd ? y1 : y0;   // P[g][kb*8 + l + 4]
            a[3] = odd ? y3 : y2;   // P[g+8][kb*8 + l + 4]
            int vr0 = (kb * 8 + l) * SVS;
            int vr1 = (kb * 8 + l + 4) * SVS;
            #pragma unroll
            for (int nt = 0; nt < 8; nt++) {
                mma8(o[nt], a, sV[vr0 + nt * 8 + g], sV[vr1 + nt * 8 + g]);
            }
        }
    }

    // final normalize + store
    lA += __shfl_xor_sync(0xffffffffu, lA, 1);
    lA += __shfl_xor_sync(0xffffffffu, lA, 2);
    lB += __shfl_xor_sync(0xffffffffu, lB, 1);
    lB += __shfl_xor_sync(0xffffffffu, lB, 2);
    float iA = 1.f / lA, iB = 1.f / lB;
    #pragma unroll
    for (int nt = 0; nt < 8; nt++) {
        float2 r0 = make_float2(o[nt][0] * iA, o[nt][1] * iA);
        float2 r1 = make_float2(o[nt][2] * iB, o[nt][3] * iB);
        *(float2*)&d_o[(size_t)(qbase + g) * CV + nt * 8 + 2 * l] = r0;
        *(float2*)&d_o[(size_t)(qbase + g + 8) * CV + nt * 8 + 2 * l] = r1;
    }
}

// ---------------- output conv + residual: out = gamma * Wo @ o + x ----------------
__global__ __launch_bounds__(256) void oconv_kernel(const float* __restrict__ x,
                                                    const float* __restrict__ gptr,
                                                    float* __restrict__ out) {
    __shared__ float sW[CV * 32];   // transposed [c][j]
    int gy = blockIdx.y;
    for (int i = threadIdx.x; i < CV * 32; i += 256) {
        int c = i >> 5, j = i & 31;
        sW[c * 32 + j] = g_Wo[(32 * gy + j) * CV + c];
    }
    __syncthreads();
    float gamma = *gptr;
    int p = blockIdx.x * 256 + threadIdx.x;
    int b = p >> 12, s = p & 4095;
    const float4* op = (const float4*)&d_o[(size_t)p * CV];

    ull acc[16];
    #pragma unroll
    for (int j = 0; j < 16; j++) acc[j] = 0ull;

    #pragma unroll 4
    for (int c4 = 0; c4 < 16; c4++) {
        float4 xv = op[c4];
        float vals[4] = {xv.x, xv.y, xv.z, xv.w};
        #pragma unroll
        for (int cc = 0; cc < 4; cc++) {
            int c = c4 * 4 + cc;
            ull X = pack2(vals[cc]);
            const float* wr = &sW[c * 32];
            #pragma unroll
            for (int j = 0; j < 8; j++) {
                ulonglong2 w = *(const ulonglong2*)(wr + j * 4);
                fma2(acc[2*j],     w.x, X);
                fma2(acc[2*j + 1], w.y, X);
            }
        }
    }
    size_t base = ((size_t)(b * CH + 32 * gy)) * HW + s;
    #pragma unroll
    for (int j = 0; j < 16; j++) {
        float2 a = unpack2(acc[j]);
        size_t i0 = base + (size_t)(2 * j) * HW;
        size_t i1 = base + (size_t)(2 * j + 1) * HW;
        out[i0] = gamma * a.x + x[i0];
        out[i1] = gamma * a.y + x[i1];
    }
}

// ---------------- launch ----------------
extern "C" void kernel_launch(void* const* d_in, const int* in_sizes, int n_in,
                              void* d_out, int out_size) {
    const float* x       = (const float*)d_in[0];
    const float* w_theta = (const float*)d_in[1];
    const float* w_phi   = (const float*)d_in[2];
    const float* w_g     = (const float*)d_in[3];
    const float* w_o     = (const float*)d_in[4];
    const float* u_theta = (const float*)d_in[5];
    const float* u_phi   = (const float*)d_in[6];
    const float* u_g     = (const float*)d_in[7];
    const float* u_o     = (const float*)d_in[8];
    const float* gamma   = (const float*)d_in[9];
    float* out = (float*)d_out;

    sn_kernel<<<4, 128>>>(w_theta, w_phi, w_g, w_o, u_theta, u_phi, u_g, u_o);
    theta_kernel<<<256, 256>>>(x);
    poolconv_kernel<16, 0><<<dim3(512, 1), 128>>>(x);
    poolconv_kernel<32, 1><<<dim3(512, 2), 128>>>(x);
    attn_mma_kernel<<<512, 256>>>();
    oconv_kernel<<<dim3(256, 4), 256>>>(x, gamma, out);
}

// round 4
// speedup vs baseline: 2.5162x; 1.0153x over previous
#include <cuda_runtime.h>
#include <cuda_bf16.h>
#include <cstdint>

// Problem constants
#define BATCH 16
#define CH    128
#define HH    64
#define WW    64
#define HW    4096          // 64*64
#define CQ    16            // C/8
#define CV    64            // C/2
#define TT    1024          // HW/4 pooled positions
#define NEG_INF (-3.402823466e38f)

typedef unsigned long long ull;

// ---------------- scratch (static device memory; no allocs allowed) ----------------
__device__ float g_Wt[CQ * CH];     // normalized theta weight  [16,128]
__device__ float g_Wp[CQ * CH];     // normalized phi weight    [16,128]
__device__ float g_Wg[CV * CH];     // normalized g weight      [64,128]
__device__ float g_Wo[CH * CV];     // normalized o weight      [128,64]

__device__ float d_theta[BATCH * HW * CQ];   // [b][s][16]
__device__ float d_phi[BATCH * TT * CQ];     // [b][t][16]
__device__ float d_g[BATCH * TT * CV];       // [b][t][64]
__device__ float d_o[BATCH * HW * CV];       // [b][s][64]

// ---------------- packed f32x2 helpers (sm_103a) ----------------
__device__ __forceinline__ ull pack2(float v) {
    ull r;
    unsigned int u = __float_as_uint(v);
    asm("mov.b64 %0, {%1, %1};" : "=l"(r) : "r"(u));
    return r;
}
__device__ __forceinline__ void fma2(ull& d, ull a, ull b) {
    asm("fma.rn.f32x2 %0, %1, %2, %0;" : "+l"(d) : "l"(a), "l"(b));
}
__device__ __forceinline__ float2 unpack2(ull v) {
    float2 r;
    r.x = __uint_as_float((unsigned int)(v & 0xffffffffull));
    r.y = __uint_as_float((unsigned int)(v >> 32));
    return r;
}

__device__ __forceinline__ unsigned to_tf32(float f) {
    unsigned r;
    asm("cvt.rna.tf32.f32 %0, %1;" : "=r"(r) : "f"(f));
    return r;
}

// mma.sync m16n8k8 tf32, C += A*B
__device__ __forceinline__ void mma8(float c[4], const unsigned a[4],
                                     unsigned b0, unsigned b1) {
    asm("mma.sync.aligned.m16n8k8.row.col.f32.tf32.tf32.f32 "
        "{%0,%1,%2,%3}, {%4,%5,%6,%7}, {%8,%9}, {%0,%1,%2,%3};"
        : "+f"(c[0]), "+f"(c[1]), "+f"(c[2]), "+f"(c[3])
        : "r"(a[0]), "r"(a[1]), "r"(a[2]), "r"(a[3]), "r"(b0), "r"(b1));
}

// cp.async helpers
__device__ __forceinline__ void cp16(unsigned dst, const void* src) {
    asm volatile("cp.async.ca.shared.global [%0], [%1], 16;" :: "r"(dst), "l"(src));
}
__device__ __forceinline__ void cp_commit() {
    asm volatile("cp.async.commit_group;");
}
__device__ __forceinline__ void cp_wait0() {
    asm volatile("cp.async.wait_group 0;" ::: "memory");
}

// ---------------- spectral norm ----------------
__device__ __forceinline__ float block_reduce_sum_128(float v, float* sred) {
    int t = threadIdx.x;
    sred[t] = v;
    __syncthreads();
    #pragma unroll
    for (int s = 64; s > 0; s >>= 1) {
        if (t < s) sred[t] += sred[t + s];
        __syncthreads();
    }
    float r = sred[0];
    __syncthreads();
    return r;
}

__global__ void sn_kernel(const float* w_theta, const float* w_phi,
                          const float* w_g, const float* w_o,
                          const float* u_theta, const float* u_phi,
                          const float* u_g, const float* u_o) {
    __shared__ float sv[128];
    __shared__ float sred[128];
    const float* W; const float* u; float* Wn; int O, I;
    switch (blockIdx.x) {
        case 0:  W = w_theta; u = u_theta; Wn = g_Wt; O = CQ; I = CH; break;
        case 1:  W = w_phi;   u = u_phi;   Wn = g_Wp; O = CQ; I = CH; break;
        case 2:  W = w_g;     u = u_g;     Wn = g_Wg; O = CV; I = CH; break;
        default: W = w_o;     u = u_o;     Wn = g_Wo; O = CH; I = CV; break;
    }
    int t = threadIdx.x;
    float vr = 0.f;
    if (t < I) {
        for (int o = 0; o < O; o++) vr += u[o] * W[o * I + t];
    }
    float nv2 = block_reduce_sum_128((t < I) ? vr * vr : 0.f, sred);
    float inv = 1.f / fmaxf(sqrtf(nv2), 1e-12f);
    if (t < I) sv[t] = vr * inv;
    __syncthreads();
    float ur = 0.f;
    if (t < O) {
        for (int i = 0; i < I; i++) ur += sv[i] * W[t * I + i];
    }
    float nu2 = block_reduce_sum_128((t < O) ? ur * ur : 0.f, sred);
    float invu = 1.f / fmaxf(sqrtf(nu2), 1e-12f);
    float sigma = block_reduce_sum_128((t < O) ? ur * ur * invu : 0.f, sred);
    float wscale = 1.f / sigma;
    for (int k = t; k < O * I; k += 128) Wn[k] = W[k] * wscale;
}

// ---------------- theta conv: [16 out] per pixel, layout [b][s][16] ----------------
__global__ __launch_bounds__(256) void theta_kernel(const float* __restrict__ x) {
    __shared__ float sW[CH * CQ];   // transposed [c][o]
    for (int i = threadIdx.x; i < CH * CQ; i += 256) {
        int c = i >> 4, o = i & 15;
        sW[i] = g_Wt[o * CH + c];
    }
    __syncthreads();
    int p = blockIdx.x * 256 + threadIdx.x;          // 0..65535
    int b = p >> 12, s = p & 4095;
    const float* xp = x + (size_t)b * CH * HW + s;
    ull acc[8];
    #pragma unroll
    for (int j = 0; j < 8; j++) acc[j] = 0ull;
    #pragma unroll 8
    for (int c = 0; c < CH; c++) {
        ull X = pack2(xp[c * HW]);
        const float* wr = &sW[c * CQ];
        #pragma unroll
        for (int j = 0; j < 4; j++) {
            ulonglong2 w = *(const ulonglong2*)(wr + j * 4);
            fma2(acc[2*j],     w.x, X);
            fma2(acc[2*j + 1], w.y, X);
        }
    }
    float4* outp = (float4*)&d_theta[(size_t)p * CQ];
    #pragma unroll
    for (int j = 0; j < 4; j++) {
        float2 a0 = unpack2(acc[2*j]);
        float2 a1 = unpack2(acc[2*j + 1]);
        outp[j] = make_float4(a0.x, a0.y, a1.x, a1.y);
    }
}

// ---------------- pooled convs: 1 thread per (pooled pos, subpixel) ----------------
template <int NOUT, int WSEL>
__global__ __launch_bounds__(128) void poolconv_kernel(const float* __restrict__ x) {
    __shared__ float sW[CH * NOUT];  // transposed [c][o]
    int ochOff = blockIdx.y * NOUT;
    const float* Wsrc = (WSEL == 0 ? g_Wp : g_Wg);
    for (int i = threadIdx.x; i < CH * NOUT; i += 128) {
        int c = i / NOUT, o = i % NOUT;
        sW[i] = Wsrc[(ochOff + o) * CH + c];
    }
    __syncthreads();
    int tid = blockIdx.x * 128 + threadIdx.x;   // 0..65535
    int pooled = tid >> 2, sub = tid & 3;       // pooled pos, subpixel
    int b = pooled >> 10, t = pooled & 1023;
    int hp = t >> 5, wp = t & 31;
    int pix = (2 * hp + (sub >> 1)) * WW + 2 * wp + (sub & 1);
    const float* xp = x + (size_t)b * CH * HW + pix;

    ull acc[NOUT / 2];
    #pragma unroll
    for (int j = 0; j < NOUT / 2; j++) acc[j] = 0ull;

    #pragma unroll 8
    for (int c = 0; c < CH; c++) {
        ull X = pack2(xp[c * HW]);
        const float* wr = &sW[c * NOUT];
        #pragma unroll
        for (int j = 0; j < NOUT / 4; j++) {
            ulonglong2 w = *(const ulonglong2*)(wr + j * 4);
            fma2(acc[2*j],     w.x, X);
            fma2(acc[2*j + 1], w.y, X);
        }
    }

    float vals[NOUT];
    #pragma unroll
    for (int j = 0; j < NOUT / 2; j++) {
        float2 f = unpack2(acc[j]);
        vals[2*j] = f.x; vals[2*j + 1] = f.y;
    }
    #pragma unroll
    for (int o = 0; o < NOUT; o++) {
        vals[o] = fmaxf(vals[o], __shfl_xor_sync(0xffffffffu, vals[o], 1));
        vals[o] = fmaxf(vals[o], __shfl_xor_sync(0xffffffffu, vals[o], 2));
    }
    if (sub == 0) {
        float* outp = (WSEL == 0) ? &d_phi[(size_t)pooled * CQ + ochOff]
                                  : &d_g[(size_t)pooled * CV + ochOff];
        #pragma unroll
        for (int o = 0; o < NOUT; o += 4)
            *(float4*)&outp[o] = make_float4(vals[o], vals[o+1], vals[o+2], vals[o+3]);
    }
}

// ---------------- attention: mma.sync tf32 flash kernel, cp.async double-buffered ----
// Block: 256 threads / 8 warps; 128 queries per block (warp = 16 query rows).
// K chunk [64x16] f32 bits in smem (stride 20), V chunk [64x64] (stride 72), 2 stages.
#define SKS 20
#define SVS 72
#define KSTG (64 * SKS)
#define VSTG (64 * SVS)
__global__ __launch_bounds__(256, 2) void attn_mma_kernel() {
    __shared__ unsigned sK[2 * KSTG];   // 10.0 KB
    __shared__ unsigned sV[2 * VSTG];   // 36.9 KB
    const int tid = threadIdx.x;
    const int w = tid >> 5, lane = tid & 31;
    const int g = lane >> 2, l = lane & 3;
    const int qbase = blockIdx.x * 128 + w * 16;
    const int b = (int)((blockIdx.x * 128) >> 12);
    const float* phib = &d_phi[(size_t)(b << 10) * CQ];
    const float* gb   = &d_g[(size_t)(b << 10) * CV];

    // per-thread cp.async source/dest (fixed across chunks except c0 offset)
    const int krow = tid >> 2, kseg = tid & 3;
    unsigned kdst;
    {
        unsigned base = (unsigned)__cvta_generic_to_shared(sK);
        kdst = base + (unsigned)((krow * SKS + kseg * 4) * 4);
    }
    unsigned vdst0;
    {
        unsigned base = (unsigned)__cvta_generic_to_shared(sV);
        vdst0 = base;
    }

    // Q fragments (A operand, 2 k-steps), tf32 (rna)
    unsigned qf[2][4];
    {
        const float* q0 = &d_theta[(size_t)(qbase + g) * CQ];
        const float* q1 = &d_theta[(size_t)(qbase + g + 8) * CQ];
        qf[0][0] = to_tf32(q0[l]);      qf[0][1] = to_tf32(q1[l]);
        qf[0][2] = to_tf32(q0[l + 4]);  qf[0][3] = to_tf32(q1[l + 4]);
        qf[1][0] = to_tf32(q0[8 + l]);  qf[1][1] = to_tf32(q1[8 + l]);
        qf[1][2] = to_tf32(q0[12 + l]); qf[1][3] = to_tf32(q1[12 + l]);
    }

    float o[8][4];
    #pragma unroll
    for (int nt = 0; nt < 8; nt++)
        #pragma unroll
        for (int j = 0; j < 4; j++) o[nt][j] = 0.f;
    float mA = NEG_INF, mB = NEG_INF, lA = 0.f, lB = 0.f;

    const unsigned s1 = (lane & ~3u) | ((unsigned)l >> 1);
    const unsigned s2 = s1 + 2;

    // ---- prologue: fill stage 0 ----
    {
        cp16(kdst, phib + krow * CQ + kseg * 4);
        #pragma unroll
        for (int r = 0; r < 4; r++) {
            int idx = tid + r * 256;
            int vrow = idx >> 4, vseg = idx & 15;
            cp16(vdst0 + (unsigned)((vrow * SVS + vseg * 4) * 4),
                 gb + vrow * CV + vseg * 4);
        }
        cp_commit();
        cp_wait0();
        __syncthreads();
    }

    for (int c0 = 0; c0 < TT; c0 += 64) {
        int stage = (c0 >> 6) & 1;
        const unsigned* cK = sK + stage * KSTG;
        const unsigned* cV = sV + stage * VSTG;

        // issue next-stage fill
        if (c0 + 64 < TT) {
            int nxt = stage ^ 1;
            int cn = c0 + 64;
            cp16(kdst + (unsigned)(nxt * KSTG * 4), phib + (cn + krow) * CQ + kseg * 4);
            unsigned vbase = vdst0 + (unsigned)(nxt * VSTG * 4);
            #pragma unroll
            for (int r = 0; r < 4; r++) {
                int idx = tid + r * 256;
                int vrow = idx >> 4, vseg = idx & 15;
                cp16(vbase + (unsigned)((vrow * SVS + vseg * 4) * 4),
                     gb + (cn + vrow) * CV + vseg * 4);
            }
            cp_commit();
        }

        // ---- S = Q @ K^T : 8 n-tiles x 2 k-steps ----
        float c[8][4];
        #pragma unroll
        for (int nt = 0; nt < 8; nt++) {
            c[nt][0] = c[nt][1] = c[nt][2] = c[nt][3] = 0.f;
            int kr = (nt * 8 + g) * SKS;
            mma8(c[nt], qf[0], cK[kr + l],     cK[kr + l + 4]);
            mma8(c[nt], qf[1], cK[kr + 8 + l], cK[kr + 12 + l]);
        }

        // ---- online softmax ----
        float cmA = NEG_INF, cmB = NEG_INF;
        #pragma unroll
        for (int nt = 0; nt < 8; nt++) {
            cmA = fmaxf(cmA, fmaxf(c[nt][0], c[nt][1]));
            cmB = fmaxf(cmB, fmaxf(c[nt][2], c[nt][3]));
        }
        cmA = fmaxf(cmA, __shfl_xor_sync(0xffffffffu, cmA, 1));
        cmA = fmaxf(cmA, __shfl_xor_sync(0xffffffffu, cmA, 2));
        cmB = fmaxf(cmB, __shfl_xor_sync(0xffffffffu, cmB, 1));
        cmB = fmaxf(cmB, __shfl_xor_sync(0xffffffffu, cmB, 2));
        float nmA = fmaxf(mA, cmA), nmB = fmaxf(mB, cmB);
        float sA = __expf(mA - nmA), sB = __expf(mB - nmB);
        mA = nmA; mB = nmB;
        lA *= sA; lB *= sB;

        unsigned p[8][4];
        #pragma unroll
        for (int nt = 0; nt < 8; nt++) {
            o[nt][0] *= sA; o[nt][1] *= sA; o[nt][2] *= sB; o[nt][3] *= sB;
            float p0 = __expf(c[nt][0] - mA);
            float p1 = __expf(c[nt][1] - mA);
            float p2 = __expf(c[nt][2] - mB);
            float p3 = __expf(c[nt][3] - mB);
            lA += p0 + p1; lB += p2 + p3;
            p[nt][0] = to_tf32(p0); p[nt][1] = to_tf32(p1);
            p[nt][2] = to_tf32(p2); p[nt][3] = to_tf32(p3);
        }

        // ---- O += P @ V : 8 k-blocks x 8 n-tiles ----
        #pragma unroll
        for (int kb = 0; kb < 8; kb++) {
            unsigned x0 = __shfl_sync(0xffffffffu, p[kb][0], s1);
            unsigned x1 = __shfl_sync(0xffffffffu, p[kb][1], s1);
            unsigned x2 = __shfl_sync(0xffffffffu, p[kb][2], s1);
            unsigned x3 = __shfl_sync(0xffffffffu, p[kb][3], s1);
            unsigned y0 = __shfl_sync(0xffffffffu, p[kb][0], s2);
            unsigned y1 = __shfl_sync(0xffffffffu, p[kb][1], s2);
            unsigned y2 = __shfl_sync(0xffffffffu, p[kb][2], s2);
            unsigned y3 = __shfl_sync(0xffffffffu, p[kb][3], s2);
            unsigned a[4];
            bool odd = (l & 1);
            a[0] = odd ? x1 : x0;   // P[g][kb*8 + l]
            a[1] = odd ? x3 : x2;   // P[g+8][kb*8 + l]
            a[2] = odd ? y1 : y0;   // P[g][kb*8 + l + 4]
            a[3] = odd ? y3 : y2;   // P[g+8][kb*8 + l + 4]
            int vr0 = (kb * 8 + l) * SVS;
            int vr1 = (kb * 8 + l + 4) * SVS;
            #pragma unroll
            for (int nt = 0; nt < 8; nt++) {
                mma8(o[nt], a, cV[vr0 + nt * 8 + g], cV[vr1 + nt * 8 + g]);
            }
        }

        cp_wait0();
        __syncthreads();
    }

    // final normalize + store
    lA += __shfl_xor_sync(0xffffffffu, lA, 1);
    lA += __shfl_xor_sync(0xffffffffu, lA, 2);
    lB += __shfl_xor_sync(0xffffffffu, lB, 1);
    lB += __shfl_xor_sync(0xffffffffu, lB, 2);
    float iA = 1.f / lA, iB = 1.f / lB;
    #pragma unroll
    for (int nt = 0; nt < 8; nt++) {
        float2 r0 = make_float2(o[nt][0] * iA, o[nt][1] * iA);
        float2 r1 = make_float2(o[nt][2] * iB, o[nt][3] * iB);
        *(float2*)&d_o[(size_t)(qbase + g) * CV + nt * 8 + 2 * l] = r0;
        *(float2*)&d_o[(size_t)(qbase + g + 8) * CV + nt * 8 + 2 * l] = r1;
    }
}

// ---------------- output conv + residual: out = gamma * Wo @ o + x ----------------
__global__ __launch_bounds__(256) void oconv_kernel(const float* __restrict__ x,
                                                    const float* __restrict__ gptr,
                                                    float* __restrict__ out) {
    __shared__ float sW[CV * 32];   // transposed [c][j]
    int gy = blockIdx.y;
    for (int i = threadIdx.x; i < CV * 32; i += 256) {
        int c = i >> 5, j = i & 31;
        sW[c * 32 + j] = g_Wo[(32 * gy + j) * CV + c];
    }
    __syncthreads();
    float gamma = *gptr;
    int p = blockIdx.x * 256 + threadIdx.x;
    int b = p >> 12, s = p & 4095;
    const float4* op = (const float4*)&d_o[(size_t)p * CV];

    ull acc[16];
    #pragma unroll
    for (int j = 0; j < 16; j++) acc[j] = 0ull;

    #pragma unroll 4
    for (int c4 = 0; c4 < 16; c4++) {
        float4 xv = op[c4];
        float vals[4] = {xv.x, xv.y, xv.z, xv.w};
        #pragma unroll
        for (int cc = 0; cc < 4; cc++) {
            int c = c4 * 4 + cc;
            ull X = pack2(vals[cc]);
            const float* wr = &sW[c * 32];
            #pragma unroll
            for (int j = 0; j < 8; j++) {
                ulonglong2 w = *(const ulonglong2*)(wr + j * 4);
                fma2(acc[2*j],     w.x, X);
                fma2(acc[2*j + 1], w.y, X);
            }
        }
    }
    size_t base = ((size_t)(b * CH + 32 * gy)) * HW + s;
    #pragma unroll
    for (int j = 0; j < 16; j++) {
        float2 a = unpack2(acc[j]);
        size_t i0 = base + (size_t)(2 * j) * HW;
        size_t i1 = base + (size_t)(2 * j + 1) * HW;
        out[i0] = gamma * a.x + x[i0];
        out[i1] = gamma * a.y + x[i1];
    }
}

// ---------------- launch ----------------
extern "C" void kernel_launch(void* const* d_in, const int* in_sizes, int n_in,
                              void* d_out, int out_size) {
    const float* x       = (const float*)d_in[0];
    const float* w_theta = (const float*)d_in[1];
    const float* w_phi   = (const float*)d_in[2];
    const float* w_g     = (const float*)d_in[3];
    const float* w_o     = (const float*)d_in[4];
    const float* u_theta = (const float*)d_in[5];
    const float* u_phi   = (const float*)d_in[6];
    const float* u_g     = (const float*)d_in[7];
    const float* u_o     = (const float*)d_in[8];
    const float* gamma   = (const float*)d_in[9];
    float* out = (float*)d_out;

    sn_kernel<<<4, 128>>>(w_theta, w_phi, w_g, w_o, u_theta, u_phi, u_g, u_o);
    theta_kernel<<<256, 256>>>(x);
    poolconv_kernel<16, 0><<<dim3(512, 1), 128>>>(x);
    poolconv_kernel<32, 1><<<dim3(512, 2), 128>>>(x);
    attn_mma_kernel<<<512, 256>>>();
    oconv_kernel<<<dim3(256, 4), 256>>>(x, gamma, out);
}